// round 1
// baseline (speedup 1.0000x reference)
#include <cuda_runtime.h>

// Problem constants (fixed for rotary_13872744366393):
//   x: (4, 8192, 1024) f32, matrix: (64,64), thetas: (32), tscale: (1),
//   invf: (32), pairs: (32,2) int32. out: (4, 8192, 1024) f32.
#define HEADS 16
#define D     64
#define ROTN  32
#define SEQ   8192

// Scratch: packed M. g_Mp[kk*64+n] = (M[2kk][n], M[2kk+1][n])  (K-pair packed)
__device__ float2 g_Mp[(D / 2) * D];

// packed f32x2 FMA (Blackwell): d = a*b + c elementwise on packed fp32 pairs
#define FMA2(d, a, b, c) \
    asm("fma.rn.f32x2 %0, %1, %2, %3;" : "=l"(d) : "l"(a), "l"(b), "l"(c))

// ---------------------------------------------------------------------------
// Kernel 1: build M = G_comb @ matrix, store packed.
// G_comb = I @ G_0 @ ... @ G_31 ; right-multiplying by G_q updates COLUMNS
// (i, j) of the accumulator:
//   col_i' = col_i*c + col_j*s ;  col_j' = -col_i*s + col_j*c
// Degenerate i==j (the JAX .at sequence leaves G[i,i] = sin): col_i' = col_i*s
// ---------------------------------------------------------------------------
__global__ void build_M_kernel(const float* __restrict__ matrix,
                               const float* __restrict__ thetas,
                               const float* __restrict__ tscale,
                               const int*   __restrict__ pairs) {
    __shared__ float Gs[64][65];   // +1 pad
    __shared__ float Mat[64][64];
    __shared__ float Msh[64][64];
    const int tid = threadIdx.x;   // 256 threads

    for (int i = tid; i < 64 * 64; i += 256)
        Mat[i >> 6][i & 63] = matrix[i];

    if (tid < 64) {
        #pragma unroll
        for (int k = 0; k < 64; k++) Gs[tid][k] = (tid == k) ? 1.0f : 0.0f;
    }
    __syncthreads();

    if (tid < 64) {
        const float ts = tscale[0];
        for (int q = 0; q < ROTN; q++) {
            const int   i  = pairs[2 * q];
            const int   j  = pairs[2 * q + 1];
            const float th = thetas[q] * ts;
            float s, c;
            sincosf(th, &s, &c);
            const float ai = Gs[tid][i];
            const float aj = Gs[tid][j];
            if (i != j) {
                Gs[tid][i] = ai * c + aj * s;
                Gs[tid][j] = -ai * s + aj * c;
            } else {
                Gs[tid][i] = ai * s;
            }
        }
    }
    __syncthreads();

    // M = G_comb @ matrix. thread -> (row r = tid>>2, n-quarter qq = tid&3)
    {
        const int r  = tid >> 2;
        const int qq = tid & 3;
        float gr[64];
        #pragma unroll
        for (int k = 0; k < 64; k++) gr[k] = Gs[r][k];
        #pragma unroll
        for (int n0 = 0; n0 < 16; n0++) {
            const int n = qq * 16 + n0;
            float acc = 0.0f;
            #pragma unroll
            for (int k = 0; k < 64; k++) acc = fmaf(gr[k], Mat[k][n], acc);
            Msh[r][n] = acc;
        }
    }
    __syncthreads();

    for (int idx = tid; idx < 32 * 64; idx += 256) {
        const int kk = idx >> 6, n = idx & 63;
        g_Mp[idx] = make_float2(Msh[2 * kk][n], Msh[2 * kk + 1][n]);
    }
}

// ---------------------------------------------------------------------------
// Kernel 2: y = v @ M via packed f32x2 FMAs, then RoPE epilogue + *sqrt(dims).
// 1 thread = 1 row (one head-vector of 64). Block = 256 threads = 16 tokens.
// ---------------------------------------------------------------------------
__global__ __launch_bounds__(256, 1)
void rotary_main(const float* __restrict__ x,
                 const float* __restrict__ invf,
                 float* __restrict__ out) {
    __shared__ unsigned long long Ms[32 * 64];  // packed M pairs, 16 KB
    __shared__ float2 sc[16 * 32];              // (sin, cos) per (local pos, freq)

    const int tid = threadIdx.x;
    const long long row0 = (long long)blockIdx.x * 256;

    // load packed M (broadcast-consumed later)
    {
        const unsigned long long* gm = (const unsigned long long*)g_Mp;
        #pragma unroll
        for (int i = 0; i < 8; i++) Ms[tid + 256 * i] = gm[tid + 256 * i];
    }

    // per-block sincos table: 16 positions x 32 freqs (2 sincosf per thread)
    {
        const int s0 = (int)((row0 % (long long)(SEQ * HEADS)) / HEADS);
        #pragma unroll
        for (int e = 0; e < 2; e++) {
            const int idx = tid * 2 + e;
            const int lp = idx >> 5, m = idx & 31;
            const float ang = (float)(s0 + lp) * invf[m];
            float sn, cs;
            sincosf(ang, &sn, &cs);
            sc[idx] = make_float2(sn, cs);
        }
    }
    __syncthreads();

    const long long row = row0 + tid;
    const float4* xv = (const float4*)(x + row * 64);

    // v packed as 32 fp32-pairs over K
    unsigned long long v2[32];
    #pragma unroll
    for (int i = 0; i < 16; i++) {
        const float4 t = xv[i];
        float2 p0 = make_float2(t.x, t.y);
        float2 p1 = make_float2(t.z, t.w);
        v2[2 * i]     = *(const unsigned long long*)&p0;
        v2[2 * i + 1] = *(const unsigned long long*)&p1;
    }

    const int lpos = tid >> 4;  // local token index within block
    float* orow = out + row * 64;

    #pragma unroll
    for (int c = 0; c < 4; c++) {
        unsigned long long acc[16];
        #pragma unroll
        for (int n = 0; n < 16; n++) acc[n] = 0ull;  // (0.0f, 0.0f)

        #pragma unroll
        for (int kk = 0; kk < 32; kk++) {
            #pragma unroll
            for (int n = 0; n < 16; n++) {
                FMA2(acc[n], v2[kk], Ms[kk * 64 + c * 16 + n], acc[n]);
            }
        }

        // epilogue: y[n] = acc[n].x + acc[n].y ; RoPE on pairs (y[2m], y[2m+1])
        float o1[8], o2[8];
        #pragma unroll
        for (int t = 0; t < 8; t++) {
            const float2 a0 = *(const float2*)&acc[2 * t];
            const float2 a1 = *(const float2*)&acc[2 * t + 1];
            const float y1 = a0.x + a0.y;
            const float y2 = a1.x + a1.y;
            const int m = c * 8 + t;
            const float2 scm = sc[lpos * 32 + m];  // (sin, cos)
            o1[t] = (y1 * scm.y - y2 * scm.x) * 32.0f;
            o2[t] = (y1 * scm.x + y2 * scm.y) * 32.0f;
        }
        *(float4*)(orow + c * 8)          = make_float4(o1[0], o1[1], o1[2], o1[3]);
        *(float4*)(orow + c * 8 + 4)      = make_float4(o1[4], o1[5], o1[6], o1[7]);
        *(float4*)(orow + 32 + c * 8)     = make_float4(o2[0], o2[1], o2[2], o2[3]);
        *(float4*)(orow + 32 + c * 8 + 4) = make_float4(o2[4], o2[5], o2[6], o2[7]);
    }
}

// ---------------------------------------------------------------------------
extern "C" void kernel_launch(void* const* d_in, const int* in_sizes, int n_in,
                              void* d_out, int out_size) {
    const float* x      = (const float*)d_in[0];
    const float* matrix = (const float*)d_in[1];
    const float* thetas = (const float*)d_in[2];
    const float* tscale = (const float*)d_in[3];
    const float* invf   = (const float*)d_in[4];
    const int*   pairs  = (const int*)d_in[5];
    float* out = (float*)d_out;

    const int nrows  = in_sizes[0] / D;      // 524288
    const int blocks = nrows / 256;          // 2048

    build_M_kernel<<<1, 256>>>(matrix, thetas, tscale, pairs);
    rotary_main<<<blocks, 256>>>(x, invf, out);
}

// round 2
// speedup vs baseline: 1.0321x; 1.0321x over previous
#include <cuda_runtime.h>

// Problem constants (fixed for rotary_13872744366393):
//   x: (4, 8192, 1024) f32, matrix: (64,64), thetas: (32), tscale: (1),
//   invf: (32), pairs: (32,2) int32. out: (4, 8192, 1024) f32.
#define HEADS 16
#define D     64
#define ROTN  32
#define SEQ   8192

// Scratch: packed M. g_Mp[kk*64+n] = (M[2kk][n], M[2kk+1][n])  (K-pair packed)
__device__ float2 g_Mp[(D / 2) * D];

// packed f32x2 FMA (Blackwell): d = a*b + c elementwise on packed fp32 pairs
#define FMA2(d, a, b, c) \
    asm("fma.rn.f32x2 %0, %1, %2, %3;" : "=l"(d) : "l"(a), "l"(b), "l"(c))

// ---------------------------------------------------------------------------
// Kernel 1: build M = G_comb @ matrix, store packed.
// G_comb = I @ G_0 @ ... @ G_31 ; right-multiplying by G_q updates COLUMNS
// (i, j) of the accumulator:
//   col_i' = col_i*c + col_j*s ;  col_j' = -col_i*s + col_j*c
// Degenerate i==j (the JAX .at sequence leaves G[i,i] = sin): col_i' = col_i*s
// ---------------------------------------------------------------------------
__global__ void build_M_kernel(const float* __restrict__ matrix,
                               const float* __restrict__ thetas,
                               const float* __restrict__ tscale,
                               const int*   __restrict__ pairs) {
    __shared__ float Gs[64][65];   // +1 pad
    __shared__ float Mat[64][64];
    __shared__ float Msh[64][64];
    const int tid = threadIdx.x;   // 256 threads

    for (int i = tid; i < 64 * 64; i += 256)
        Mat[i >> 6][i & 63] = matrix[i];

    if (tid < 64) {
        #pragma unroll
        for (int k = 0; k < 64; k++) Gs[tid][k] = (tid == k) ? 1.0f : 0.0f;
    }
    __syncthreads();

    if (tid < 64) {
        const float ts = tscale[0];
        for (int q = 0; q < ROTN; q++) {
            const int   i  = pairs[2 * q];
            const int   j  = pairs[2 * q + 1];
            const float th = thetas[q] * ts;
            float s, c;
            sincosf(th, &s, &c);
            const float ai = Gs[tid][i];
            const float aj = Gs[tid][j];
            if (i != j) {
                Gs[tid][i] = ai * c + aj * s;
                Gs[tid][j] = -ai * s + aj * c;
            } else {
                Gs[tid][i] = ai * s;
            }
        }
    }
    __syncthreads();

    // M = G_comb @ matrix. thread -> (row r = tid>>2, n-quarter qq = tid&3)
    {
        const int r  = tid >> 2;
        const int qq = tid & 3;
        float gr[64];
        #pragma unroll
        for (int k = 0; k < 64; k++) gr[k] = Gs[r][k];
        #pragma unroll
        for (int n0 = 0; n0 < 16; n0++) {
            const int n = qq * 16 + n0;
            float acc = 0.0f;
            #pragma unroll
            for (int k = 0; k < 64; k++) acc = fmaf(gr[k], Mat[k][n], acc);
            Msh[r][n] = acc;
        }
    }
    __syncthreads();

    for (int idx = tid; idx < 32 * 64; idx += 256) {
        const int kk = idx >> 6, n = idx & 63;
        g_Mp[idx] = make_float2(Msh[2 * kk][n], Msh[2 * kk + 1][n]);
    }
}

// ---------------------------------------------------------------------------
// Kernel 2: y = v @ M via packed f32x2 FMAs, then RoPE epilogue + *sqrt(dims).
// 1 thread = 1 row (one head-vector of 64). Block = 256 threads = 16 tokens.
// LDS.128 (ulonglong2) fetches M pairs for two adjacent outputs -> 2 FMA2s
// per shared-memory instruction (LDS issue rate was the R1 bottleneck).
// ---------------------------------------------------------------------------
__global__ __launch_bounds__(256, 2)
void rotary_main(const float* __restrict__ x,
                 const float* __restrict__ invf,
                 float* __restrict__ out) {
    __shared__ __align__(16) unsigned long long Ms[32 * 64];  // packed M, 16 KB
    __shared__ float2 sc[16 * 32];              // (sin, cos) per (local pos, freq)

    const int tid = threadIdx.x;
    const long long row0 = (long long)blockIdx.x * 256;

    // load packed M (broadcast-consumed later), vectorized 16B
    {
        const ulonglong2* gm = (const ulonglong2*)g_Mp;
        ulonglong2* sm = (ulonglong2*)Ms;
        #pragma unroll
        for (int i = 0; i < 4; i++) sm[tid + 256 * i] = gm[tid + 256 * i];
    }

    // per-block sincos table: 16 positions x 32 freqs (2 sincosf per thread)
    {
        const int s0 = (int)((row0 % (long long)(SEQ * HEADS)) / HEADS);
        #pragma unroll
        for (int e = 0; e < 2; e++) {
            const int idx = tid * 2 + e;
            const int lp = idx >> 5, m = idx & 31;
            const float ang = (float)(s0 + lp) * invf[m];
            float sn, cs;
            sincosf(ang, &sn, &cs);
            sc[idx] = make_float2(sn, cs);
        }
    }
    __syncthreads();

    const long long row = row0 + tid;
    const float4* xv = (const float4*)(x + row * 64);

    // v packed as 32 fp32-pairs over K
    unsigned long long v2[32];
    #pragma unroll
    for (int i = 0; i < 16; i++) {
        const float4 t = xv[i];
        float2 p0 = make_float2(t.x, t.y);
        float2 p1 = make_float2(t.z, t.w);
        v2[2 * i]     = *(const unsigned long long*)&p0;
        v2[2 * i + 1] = *(const unsigned long long*)&p1;
    }

    const int lpos = tid >> 4;  // local token index within block
    float* orow = out + row * 64;

    #pragma unroll
    for (int c = 0; c < 4; c++) {
        unsigned long long acc[16];
        #pragma unroll
        for (int n = 0; n < 16; n++) acc[n] = 0ull;  // (0.0f, 0.0f)

        #pragma unroll
        for (int kk = 0; kk < 32; kk++) {
            const ulonglong2* mrow =
                (const ulonglong2*)&Ms[kk * 64 + c * 16];
            #pragma unroll
            for (int np = 0; np < 8; np++) {
                const ulonglong2 m = mrow[np];      // LDS.128: M for outputs 2np, 2np+1
                FMA2(acc[2 * np],     v2[kk], m.x, acc[2 * np]);
                FMA2(acc[2 * np + 1], v2[kk], m.y, acc[2 * np + 1]);
            }
        }

        // epilogue: y[n] = acc[n].x + acc[n].y ; RoPE on pairs (y[2m], y[2m+1])
        float o1[8], o2[8];
        #pragma unroll
        for (int t = 0; t < 8; t++) {
            const float2 a0 = *(const float2*)&acc[2 * t];
            const float2 a1 = *(const float2*)&acc[2 * t + 1];
            const float y1 = a0.x + a0.y;
            const float y2 = a1.x + a1.y;
            const int m = c * 8 + t;
            const float2 scm = sc[lpos * 32 + m];  // (sin, cos)
            o1[t] = (y1 * scm.y - y2 * scm.x) * 32.0f;
            o2[t] = (y1 * scm.x + y2 * scm.y) * 32.0f;
        }
        *(float4*)(orow + c * 8)          = make_float4(o1[0], o1[1], o1[2], o1[3]);
        *(float4*)(orow + c * 8 + 4)      = make_float4(o1[4], o1[5], o1[6], o1[7]);
        *(float4*)(orow + 32 + c * 8)     = make_float4(o2[0], o2[1], o2[2], o2[3]);
        *(float4*)(orow + 32 + c * 8 + 4) = make_float4(o2[4], o2[5], o2[6], o2[7]);
    }
}

// ---------------------------------------------------------------------------
extern "C" void kernel_launch(void* const* d_in, const int* in_sizes, int n_in,
                              void* d_out, int out_size) {
    const float* x      = (const float*)d_in[0];
    const float* matrix = (const float*)d_in[1];
    const float* thetas = (const float*)d_in[2];
    const float* tscale = (const float*)d_in[3];
    const float* invf   = (const float*)d_in[4];
    const int*   pairs  = (const int*)d_in[5];
    float* out = (float*)d_out;

    const int nrows  = in_sizes[0] / D;      // 524288
    const int blocks = nrows / 256;          // 2048

    build_M_kernel<<<1, 256>>>(matrix, thetas, tscale, pairs);
    rotary_main<<<blocks, 256>>>(x, invf, out);
}

// round 4
// speedup vs baseline: 1.3840x; 1.3410x over previous
#include <cuda_runtime.h>
#include <cstdint>

// Problem constants (fixed for rotary_13872744366393):
//   x: (4, 8192, 1024) f32, matrix: (64,64), thetas: (32), tscale: (1),
//   invf: (32), pairs: (32,2) int32. out: (4, 8192, 1024) f32.
#define HEADS 16
#define D     64
#define ROTN  32
#define SEQ   8192

typedef unsigned long long u64;

// B = M packed for the mainloop: g_Bp[h][kk][c] = (M[2kk][8h+c], M[2kk+1][8h+c])
// padded to 258 u64 per colg block (2064 B) for conflict-free smem LDS.128.
#define B_BLK_U64 258
__device__ u64 g_Bp[8 * B_BLK_U64];

// packed f32x2 FMA (Blackwell): d = a*b + c elementwise on packed fp32 pairs
#define FMA2(d, a, b, c) \
    asm("fma.rn.f32x2 %0, %1, %2, %3;" : "=l"(d) : "l"(a), "l"(b), "l"(c))

// ---------------------------------------------------------------------------
// Kernel 1: build M = G_comb @ matrix, emit packed B.
// G_comb = I @ G_0 @ ... @ G_31 ; right-multiplying by G_q updates COLUMNS:
//   col_i' = col_i*c + col_j*s ;  col_j' = -col_i*s + col_j*c
// Degenerate i==j (JAX .at sequence leaves G[i,i] = sin): col_i' = col_i*s
// ---------------------------------------------------------------------------
__global__ void build_M_kernel(const float* __restrict__ matrix,
                               const float* __restrict__ thetas,
                               const float* __restrict__ tscale,
                               const int*   __restrict__ pairs) {
    __shared__ float Gs[64][65];
    __shared__ float Mat[64][64];
    __shared__ float Msh[64][64];
    const int tid = threadIdx.x;   // 256 threads

    for (int i = tid; i < 64 * 64; i += 256)
        Mat[i >> 6][i & 63] = matrix[i];

    if (tid < 64) {
        #pragma unroll
        for (int k = 0; k < 64; k++) Gs[tid][k] = (tid == k) ? 1.0f : 0.0f;
    }
    __syncthreads();

    if (tid < 64) {
        const float ts = tscale[0];
        for (int q = 0; q < ROTN; q++) {
            const int   i  = pairs[2 * q];
            const int   j  = pairs[2 * q + 1];
            const float th = thetas[q] * ts;
            float s, c;
            sincosf(th, &s, &c);
            const float ai = Gs[tid][i];
            const float aj = Gs[tid][j];
            if (i != j) {
                Gs[tid][i] = ai * c + aj * s;
                Gs[tid][j] = -ai * s + aj * c;
            } else {
                Gs[tid][i] = ai * s;
            }
        }
    }
    __syncthreads();

    {
        const int r  = tid >> 2;
        const int qq = tid & 3;
        float gr[64];
        #pragma unroll
        for (int k = 0; k < 64; k++) gr[k] = Gs[r][k];
        #pragma unroll
        for (int n0 = 0; n0 < 16; n0++) {
            const int n = qq * 16 + n0;
            float acc = 0.0f;
            #pragma unroll
            for (int k = 0; k < 64; k++) acc = fmaf(gr[k], Mat[k][n], acc);
            Msh[r][n] = acc;
        }
    }
    __syncthreads();

    // pack: g_Bp[h*258 + kk*8 + c] = (M[2kk][8h+c], M[2kk+1][8h+c])
    for (int idx = tid; idx < 8 * 32 * 8; idx += 256) {
        const int h  = idx >> 8;
        const int kk = (idx >> 3) & 31;
        const int c  = idx & 7;
        const int n  = 8 * h + c;
        float2 p = make_float2(Msh[2 * kk][n], Msh[2 * kk + 1][n]);
        g_Bp[h * B_BLK_U64 + kk * 8 + c] = *(const u64*)&p;
    }
}

// ---------------------------------------------------------------------------
// Kernel 2: register-tiled f32x2 GEMM (8 rows x 8 cols per thread) + RoPE.
// CTA = 128 threads = 128 rows (8 tokens). warp w: rows [w*32, w*32+32);
// lane = rowg(g: bits 4:3) x colg(h: bits 2:0). Thread: rows r0..r0+7,
// cols 8h..8h+7.
// smem: A rows @ 264B stride (bank-spread), B packed blocks @ 2064B.
// ---------------------------------------------------------------------------
#define A_STRIDE 264
#define SM_A     0
#define SM_B     (128 * A_STRIDE)                 // 33792
#define SM_SC    (SM_B + 8 * B_BLK_U64 * 8)       // 33792 + 16512 = 50304
#define SMEM_DYN (SM_SC + 8 * 32 * 8)             // + 2048 = 52352

__global__ __launch_bounds__(128, 3)
void rotary_f2(const float* __restrict__ x,
               const float* __restrict__ invf,
               float* __restrict__ out) {
    extern __shared__ __align__(16) char dsm[];
    float2* sc = (float2*)(dsm + SM_SC);

    const int tid  = threadIdx.x;
    const int w    = tid >> 5;
    const int lane = tid & 31;
    const int g    = lane >> 3;     // row group 0..3
    const int h    = lane & 7;      // col group 0..7

    // ---- stage A: 128 rows x 256B, coalesced LDG.128 -> 2x STS.64 ----
    {
        const uint4* xg = (const uint4*)(x + (size_t)blockIdx.x * 128 * 64);
        #pragma unroll
        for (int i = 0; i < 16; i++) {
            const int idx = i * 128 + tid;        // u128 chunk id, 2048 total
            const int row = idx >> 4;
            const int kq  = idx & 15;             // 16B chunk within row
            const uint4 v = xg[idx];
            u64* dst = (u64*)(dsm + SM_A + row * A_STRIDE + kq * 16);
            u64 lo = ((u64)v.y << 32) | v.x;
            u64 hi = ((u64)v.w << 32) | v.z;
            dst[0] = lo;
            dst[1] = hi;
        }
    }

    // ---- stage B: copy packed M (2064 u64) ----
    {
        u64* bs = (u64*)(dsm + SM_B);
        #pragma unroll
        for (int i = 0; i < 17; i++) {
            const int idx = tid + 128 * i;
            if (idx < 8 * B_BLK_U64) bs[idx] = g_Bp[idx];
        }
    }

    // ---- sincos table: 8 tokens x 32 freqs ----
    {
        #pragma unroll
        for (int e = 0; e < 2; e++) {
            const int idx = tid * 2 + e;          // 256 entries
            const int t = idx >> 5, m = idx & 31;
            const int pos = (blockIdx.x * 8 + t) & (SEQ - 1);
            float sn, cs;
            sincosf((float)pos * invf[m], &sn, &cs);
            sc[idx] = make_float2(sn, cs);
        }
    }
    __syncthreads();

    // ---- mainloop: 8x8 register tile, k-pair packed f32x2 ----
    const int r0 = w * 32 + g * 8;
    const char* abase = dsm + SM_A + r0 * A_STRIDE;
    const char* bbase = dsm + SM_B + h * (B_BLK_U64 * 8);

    u64 acc[64];
    #pragma unroll
    for (int i = 0; i < 64; i++) acc[i] = 0ull;

    #pragma unroll 4
    for (int kk = 0; kk < 32; kk++) {
        u64 au[8];
        #pragma unroll
        for (int r = 0; r < 8; r++)
            au[r] = *(const u64*)(abase + r * A_STRIDE + kk * 8);
        u64 bu[8];
        #pragma unroll
        for (int j = 0; j < 4; j++) {
            const ulonglong2 b2 = *(const ulonglong2*)(bbase + kk * 64 + j * 16);
            bu[2 * j]     = b2.x;
            bu[2 * j + 1] = b2.y;
        }
        #pragma unroll
        for (int r = 0; r < 8; r++) {
            #pragma unroll
            for (int c = 0; c < 8; c++) {
                FMA2(acc[r * 8 + c], au[r], bu[c], acc[r * 8 + c]);
            }
        }
    }

    // ---- epilogue: hsum over k halves, RoPE, *sqrt(1024)=32, STG ----
    const int tok_local = r0 >> 4;                // all 8 rows in one token
    float2 scm[4];
    #pragma unroll
    for (int p = 0; p < 4; p++) scm[p] = sc[tok_local * 32 + 4 * h + p];

    float* obase = out + ((size_t)blockIdx.x * 128 + r0) * 64;
    #pragma unroll
    for (int r = 0; r < 8; r++) {
        float o1[4], o2[4];
        #pragma unroll
        for (int p = 0; p < 4; p++) {
            const float2 a0 = *(const float2*)&acc[r * 8 + 2 * p];
            const float2 a1 = *(const float2*)&acc[r * 8 + 2 * p + 1];
            const float y1 = a0.x + a0.y;
            const float y2 = a1.x + a1.y;
            o1[p] = (y1 * scm[p].y - y2 * scm[p].x) * 32.0f;
            o2[p] = (y1 * scm[p].x + y2 * scm[p].y) * 32.0f;
        }
        float* orow = obase + r * 64;
        *(float4*)(orow + 4 * h)      = make_float4(o1[0], o1[1], o1[2], o1[3]);
        *(float4*)(orow + 32 + 4 * h) = make_float4(o2[0], o2[1], o2[2], o2[3]);
    }
}

// ---------------------------------------------------------------------------
extern "C" void kernel_launch(void* const* d_in, const int* in_sizes, int n_in,
                              void* d_out, int out_size) {
    const float* x      = (const float*)d_in[0];
    const float* matrix = (const float*)d_in[1];
    const float* thetas = (const float*)d_in[2];
    const float* tscale = (const float*)d_in[3];
    const float* invf   = (const float*)d_in[4];
    const int*   pairs  = (const int*)d_in[5];
    float* out = (float*)d_out;

    static bool attr_set = false;
    if (!attr_set) {
        cudaFuncSetAttribute(rotary_f2,
                             cudaFuncAttributeMaxDynamicSharedMemorySize,
                             SMEM_DYN);
        attr_set = true;
    }

    const int nrows  = in_sizes[0] / D;      // 524288
    const int blocks = nrows / 128;          // 4096

    build_M_kernel<<<1, 256>>>(matrix, thetas, tscale, pairs);
    rotary_f2<<<blocks, 128, SMEM_DYN>>>(x, invf, out);
}

// round 5
// speedup vs baseline: 1.4097x; 1.0186x over previous
#include <cuda_runtime.h>
#include <cstdint>

// Problem constants (fixed for rotary_13872744366393):
//   x: (4, 8192, 1024) f32, matrix: (64,64), thetas: (32), tscale: (1),
//   invf: (32), pairs: (32,2) int32. out: (4, 8192, 1024) f32.
#define HEADS 16
#define D     64
#define ROTN  32
#define SEQ   8192

typedef unsigned long long u64;

// B = M packed for the mainloop: g_Bp[h][kk][c] = (M[2kk][8h+c], M[2kk+1][8h+c])
// padded to 258 u64 per colg block (2064 B) for conflict-free smem LDS.128.
#define B_BLK_U64 258
__device__ u64 g_Bp[8 * B_BLK_U64];

// packed f32x2 FMA (Blackwell): d = a*b + d. "+l" lets ptxas keep the
// accumulator in place (R4's "=l" version forced a MOV pair per FFMA2,
// saturating the alu pipe at 44%).
#define FMA2(d, a, b) \
    asm("fma.rn.f32x2 %0, %1, %2, %0;" : "+l"(d) : "l"(a), "l"(b))

// ---------------------------------------------------------------------------
// Kernel 1: build M = G_comb @ matrix, emit packed B.
// G_comb = I @ G_0 @ ... @ G_31 ; right-multiplying by G_q updates COLUMNS:
//   col_i' = col_i*c + col_j*s ;  col_j' = -col_i*s + col_j*c
// Degenerate i==j (JAX .at sequence leaves G[i,i] = sin): col_i' = col_i*s
// ---------------------------------------------------------------------------
__global__ void build_M_kernel(const float* __restrict__ matrix,
                               const float* __restrict__ thetas,
                               const float* __restrict__ tscale,
                               const int*   __restrict__ pairs) {
    __shared__ float Gs[64][65];
    __shared__ float Mat[64][64];
    __shared__ float Msh[64][64];
    __shared__ float ssin[ROTN], scos[ROTN];
    __shared__ int   sij[ROTN][2];
    const int tid = threadIdx.x;   // 256 threads

    for (int i = tid; i < 64 * 64; i += 256)
        Mat[i >> 6][i & 63] = matrix[i];

    if (tid < ROTN) {                      // sincos once, not per-row
        const float th = thetas[tid] * tscale[0];
        float s, c;
        sincosf(th, &s, &c);
        ssin[tid] = s;
        scos[tid] = c;
        sij[tid][0] = pairs[2 * tid];
        sij[tid][1] = pairs[2 * tid + 1];
    }
    if (tid < 64) {
        #pragma unroll
        for (int k = 0; k < 64; k++) Gs[tid][k] = (tid == k) ? 1.0f : 0.0f;
    }
    __syncthreads();

    if (tid < 64) {
        for (int q = 0; q < ROTN; q++) {
            const int   i = sij[q][0];
            const int   j = sij[q][1];
            const float s = ssin[q];
            const float c = scos[q];
            const float ai = Gs[tid][i];
            const float aj = Gs[tid][j];
            if (i != j) {
                Gs[tid][i] = ai * c + aj * s;
                Gs[tid][j] = -ai * s + aj * c;
            } else {
                Gs[tid][i] = ai * s;
            }
        }
    }
    __syncthreads();

    {
        const int r  = tid >> 2;
        const int qq = tid & 3;
        float gr[64];
        #pragma unroll
        for (int k = 0; k < 64; k++) gr[k] = Gs[r][k];
        #pragma unroll
        for (int n0 = 0; n0 < 16; n0++) {
            const int n = qq * 16 + n0;
            float acc = 0.0f;
            #pragma unroll
            for (int k = 0; k < 64; k++) acc = fmaf(gr[k], Mat[k][n], acc);
            Msh[r][n] = acc;
        }
    }
    __syncthreads();

    // pack: g_Bp[h*258 + kk*8 + c] = (M[2kk][8h+c], M[2kk+1][8h+c])
    for (int idx = tid; idx < 8 * 32 * 8; idx += 256) {
        const int h  = idx >> 8;
        const int kk = (idx >> 3) & 31;
        const int c  = idx & 7;
        const int n  = 8 * h + c;
        float2 p = make_float2(Msh[2 * kk][n], Msh[2 * kk + 1][n]);
        g_Bp[h * B_BLK_U64 + kk * 8 + c] = *(const u64*)&p;
    }
}

// ---------------------------------------------------------------------------
// Kernel 2: register-tiled f32x2 GEMM (8 rows x 8 cols per thread) + RoPE.
// CTA = 128 threads = 128 rows (8 tokens). warp w: rows [w*32, w*32+32);
// lane = rowg(g: bits 4:3) x colg(h: bits 2:0). Thread: rows r0..r0+7,
// cols 8h..8h+7.
// smem: A rows @ 264B stride (bank-spread), B packed blocks @ 2064B.
// ---------------------------------------------------------------------------
#define A_STRIDE 264
#define SM_A     0
#define SM_B     (128 * A_STRIDE)                 // 33792
#define SM_SC    (SM_B + 8 * B_BLK_U64 * 8)       // 33792 + 16512 = 50304
#define SMEM_DYN (SM_SC + 8 * 32 * 8)             // + 2048 = 52352

__global__ __launch_bounds__(128, 3)
void rotary_f2(const float* __restrict__ x,
               const float* __restrict__ invf,
               float* __restrict__ out) {
    extern __shared__ __align__(16) char dsm[];
    float2* sc = (float2*)(dsm + SM_SC);

    const int tid  = threadIdx.x;
    const int w    = tid >> 5;
    const int lane = tid & 31;
    const int g    = lane >> 3;     // row group 0..3
    const int h    = lane & 7;      // col group 0..7

    // ---- stage A: 128 rows x 256B, coalesced LDG.128 -> 2x STS.64 ----
    {
        const uint4* xg = (const uint4*)(x + (size_t)blockIdx.x * 128 * 64);
        #pragma unroll
        for (int i = 0; i < 16; i++) {
            const int idx = i * 128 + tid;        // u128 chunk id, 2048 total
            const int row = idx >> 4;
            const int kq  = idx & 15;             // 16B chunk within row
            const uint4 v = xg[idx];
            u64* dst = (u64*)(dsm + SM_A + row * A_STRIDE + kq * 16);
            u64 lo = ((u64)v.y << 32) | v.x;
            u64 hi = ((u64)v.w << 32) | v.z;
            dst[0] = lo;
            dst[1] = hi;
        }
    }

    // ---- stage B: copy packed M (2064 u64) ----
    {
        u64* bs = (u64*)(dsm + SM_B);
        #pragma unroll
        for (int i = 0; i < 17; i++) {
            const int idx = tid + 128 * i;
            if (idx < 8 * B_BLK_U64) bs[idx] = g_Bp[idx];
        }
    }

    // ---- sincos table: 8 tokens x 32 freqs ----
    {
        #pragma unroll
        for (int e = 0; e < 2; e++) {
            const int idx = tid * 2 + e;          // 256 entries
            const int t = idx >> 5, m = idx & 31;
            const int pos = (blockIdx.x * 8 + t) & (SEQ - 1);
            float sn, cs;
            sincosf((float)pos * invf[m], &sn, &cs);
            sc[idx] = make_float2(sn, cs);
        }
    }
    __syncthreads();

    // ---- mainloop: 8x8 register tile, k-pair packed f32x2 ----
    const int r0 = w * 32 + g * 8;
    const char* abase = dsm + SM_A + r0 * A_STRIDE;
    const char* bbase = dsm + SM_B + h * (B_BLK_U64 * 8);

    u64 acc[64];
    #pragma unroll
    for (int i = 0; i < 64; i++) acc[i] = 0ull;

    #pragma unroll 4
    for (int kk = 0; kk < 32; kk++) {
        u64 au[8];
        #pragma unroll
        for (int r = 0; r < 8; r++)
            au[r] = *(const u64*)(abase + r * A_STRIDE + kk * 8);
        u64 bu[8];
        #pragma unroll
        for (int j = 0; j < 4; j++) {
            const ulonglong2 b2 = *(const ulonglong2*)(bbase + kk * 64 + j * 16);
            bu[2 * j]     = b2.x;
            bu[2 * j + 1] = b2.y;
        }
        #pragma unroll
        for (int r = 0; r < 8; r++) {
            #pragma unroll
            for (int c = 0; c < 8; c++) {
                FMA2(acc[r * 8 + c], au[r], bu[c]);
            }
        }
    }

    // ---- epilogue: hsum over k halves, RoPE, *sqrt(1024)=32, STG ----
    const int tok_local = r0 >> 4;                // all 8 rows in one token
    float2 scm[4];
    #pragma unroll
    for (int p = 0; p < 4; p++) scm[p] = sc[tok_local * 32 + 4 * h + p];

    float* obase = out + ((size_t)blockIdx.x * 128 + r0) * 64;
    #pragma unroll
    for (int r = 0; r < 8; r++) {
        float o1[4], o2[4];
        #pragma unroll
        for (int p = 0; p < 4; p++) {
            const float2 a0 = *(const float2*)&acc[r * 8 + 2 * p];
            const float2 a1 = *(const float2*)&acc[r * 8 + 2 * p + 1];
            const float y1 = a0.x + a0.y;
            const float y2 = a1.x + a1.y;
            o1[p] = (y1 * scm[p].y - y2 * scm[p].x) * 32.0f;
            o2[p] = (y1 * scm[p].x + y2 * scm[p].y) * 32.0f;
        }
        float* orow = obase + r * 64;
        *(float4*)(orow + 4 * h)      = make_float4(o1[0], o1[1], o1[2], o1[3]);
        *(float4*)(orow + 32 + 4 * h) = make_float4(o2[0], o2[1], o2[2], o2[3]);
    }
}

// ---------------------------------------------------------------------------
extern "C" void kernel_launch(void* const* d_in, const int* in_sizes, int n_in,
                              void* d_out, int out_size) {
    const float* x      = (const float*)d_in[0];
    const float* matrix = (const float*)d_in[1];
    const float* thetas = (const float*)d_in[2];
    const float* tscale = (const float*)d_in[3];
    const float* invf   = (const float*)d_in[4];
    const int*   pairs  = (const int*)d_in[5];
    float* out = (float*)d_out;

    static bool attr_set = false;
    if (!attr_set) {
        cudaFuncSetAttribute(rotary_f2,
                             cudaFuncAttributeMaxDynamicSharedMemorySize,
                             SMEM_DYN);
        attr_set = true;
    }

    const int nrows  = in_sizes[0] / D;      // 524288
    const int blocks = nrows / 128;          // 4096

    build_M_kernel<<<1, 256>>>(matrix, thetas, tscale, pairs);
    rotary_f2<<<blocks, 128, SMEM_DYN>>>(x, invf, out);
}